// round 2
// baseline (speedup 1.0000x reference)
#include <cuda_runtime.h>

// Seq2seq LSTM, persistent single-kernel implementation.
// B=32, H=2048, T_IN=128, T_OUT=64, IO=1.
// 128 blocks x 256 threads, all resident -> software grid barrier per step.
// Each thread owns (2 batches x 1 hidden unit x 4 gates); cell state c stays in registers.

#define GRID   128
#define NTHR   256
#define BSZ    32
#define HID    2048
#define TIN    128
#define TOUT   64
#define UPB    16            // hidden units per block (128*16 = 2048)
#define KC     256           // k-chunk staged in smem
#define KSTR   260           // padded stride (260*4 = 1040 bytes, 16B aligned, bank-skewed)
#define TSTEPS (TIN + TOUT)  // 192

__device__ __align__(16) float g_hA[BSZ * HID];
__device__ __align__(16) float g_hB[BSZ * HID];
__device__ float    g_yblk[GRID * BSZ];
__device__ unsigned g_bar;
__device__ unsigned g_fin;

// Packed dual-FMA: d.{x,y} += a.{x,y} * b.{x,y}  (Blackwell f32x2 pipe, 2 MACs/lane-op)
__device__ __forceinline__ void fma2(unsigned long long& d,
                                     unsigned long long a,
                                     unsigned long long b) {
    asm("fma.rn.f32x2 %0, %1, %2, %0;" : "+l"(d) : "l"(a), "l"(b));
}

__device__ __forceinline__ float hsum2(unsigned long long v) {
    return __uint_as_float((unsigned)v) + __uint_as_float((unsigned)(v >> 32));
}

__device__ __forceinline__ float sigmoidf(float v) {
    return 1.0f / (1.0f + __expf(-v));
}

// Grid-wide barrier: monotonically increasing counter, reset at kernel end.
__device__ __forceinline__ void grid_barrier(int n) {
    __syncthreads();
    if (threadIdx.x == 0) {
        __threadfence();
        atomicAdd(&g_bar, 1u);
        unsigned target = (unsigned)n * GRID;
        unsigned v;
        do {
            asm volatile("ld.acquire.gpu.global.u32 %0, [%1];"
                         : "=r"(v) : "l"(&g_bar) : "memory");
        } while (v < target);
    }
    __syncthreads();
}

__global__ void __launch_bounds__(NTHR, 1)
lstm_seq2seq_kernel(const float* __restrict__ x,
                    const float* __restrict__ eWih, const float* __restrict__ eWhh,
                    const float* __restrict__ eb,
                    const float* __restrict__ dWih, const float* __restrict__ dWhh,
                    const float* __restrict__ db,
                    const float* __restrict__ fcW,  const float* __restrict__ fcb,
                    float* __restrict__ out) {
    __shared__ __align__(16) float h_s[BSZ][KSTR];
    __shared__ float ypart[UPB][BSZ + 1];
    __shared__ float y_s[BSZ];

    const int tid = threadIdx.x;
    const int blk = blockIdx.x;
    const int b1  = tid & 15;        // batches 0..15
    const int b2  = b1 + 16;         // batches 16..31
    const int ul  = tid >> 4;        // 0..15 local unit
    const int u   = blk * UPB + ul;  // global hidden unit

    // zero initial h (buffer A); c lives in registers
    g_hA[b1 * HID + u] = 0.0f;
    g_hA[b2 * HID + u] = 0.0f;

    float c1 = 0.0f, c2 = 0.0f;
    const float fcb0 = fcb[0];
    const float fcw  = fcW[u];

    // per-phase weight state
    const float* r0 = 0; const float* r1 = 0; const float* r2 = 0; const float* r3 = 0;
    float wih0 = 0, wih1 = 0, wih2 = 0, wih3 = 0;
    float bv0 = 0, bv1 = 0, bv2 = 0, bv3 = 0;

    int bars = 0;
    grid_barrier(++bars);  // h init visible everywhere

    float inp1 = 0.0f, inp2 = 0.0f;

    for (int t = 0; t < TSTEPS; ++t) {
        const bool enc = (t < TIN);
        if (t == 0 || t == TIN) {
            const float* Wih = enc ? eWih : dWih;
            const float* Whh = enc ? eWhh : dWhh;
            const float* bv  = enc ? eb   : db;
            const size_t HH = (size_t)HID * HID;
            r0 = Whh + (size_t)u * HID;
            r1 = r0 + HH; r2 = r1 + HH; r3 = r2 + HH;
            wih0 = Wih[u]; wih1 = Wih[HID + u]; wih2 = Wih[2 * HID + u]; wih3 = Wih[3 * HID + u];
            bv0  = bv[u];  bv1  = bv[HID + u];  bv2  = bv[2 * HID + u];  bv3  = bv[3 * HID + u];
        }

        // decoder input: reduce y from previous step's partials
        if (!enc && t > TIN) {
            if (tid < BSZ) {
                float s = fcb0;
                #pragma unroll 8
                for (int g = 0; g < GRID; ++g) s += g_yblk[g * BSZ + tid];
                y_s[tid] = s;
                if (blk == 0) out[tid * TOUT + (t - 1 - TIN)] = s;
            }
            __syncthreads();
            inp1 = y_s[b1];
            inp2 = y_s[b2];
        } else if (t == TIN) {
            inp1 = x[b1 * TIN + (TIN - 1)];
            inp2 = x[b2 * TIN + (TIN - 1)];
        } else {
            inp1 = x[b1 * TIN + t];
            inp2 = x[b2 * TIN + t];
        }

        const float* hin = (t & 1) ? g_hB : g_hA;
        float*       hout = (t & 1) ? g_hA : g_hB;

        // accumulate gates: [i,f,g,o] x [b1,b2], packed pairwise over k
        unsigned long long a00 = 0, a10 = 0, a20 = 0, a30 = 0;
        unsigned long long a01 = 0, a11 = 0, a21 = 0, a31 = 0;

        for (int kc = 0; kc < HID; kc += KC) {
            __syncthreads();  // protect h_s reuse
            // cooperative stage of h chunk: 32 rows x 256 cols
            #pragma unroll
            for (int i = 0; i < 8; ++i) {
                int f4 = tid + i * NTHR;       // float4 index, 0..2047
                int bb = f4 >> 6;              // row (batch)
                int c4 = f4 & 63;              // float4 col within chunk
                float4 v = *reinterpret_cast<const float4*>(hin + bb * HID + kc + c4 * 4);
                *reinterpret_cast<float4*>(&h_s[bb][c4 * 4]) = v;
            }
            __syncthreads();

            const float* p0 = r0 + kc;
            const float* p1 = r1 + kc;
            const float* p2 = r2 + kc;
            const float* p3 = r3 + kc;

            #pragma unroll 4
            for (int k4 = 0; k4 < KC; k4 += 4) {
                ulonglong2 w0 = *reinterpret_cast<const ulonglong2*>(p0 + k4);
                ulonglong2 w1 = *reinterpret_cast<const ulonglong2*>(p1 + k4);
                ulonglong2 w2 = *reinterpret_cast<const ulonglong2*>(p2 + k4);
                ulonglong2 w3 = *reinterpret_cast<const ulonglong2*>(p3 + k4);
                ulonglong2 hv1 = *reinterpret_cast<const ulonglong2*>(&h_s[b1][k4]);
                ulonglong2 hv2 = *reinterpret_cast<const ulonglong2*>(&h_s[b2][k4]);
                fma2(a00, w0.x, hv1.x); fma2(a10, w1.x, hv1.x);
                fma2(a20, w2.x, hv1.x); fma2(a30, w3.x, hv1.x);
                fma2(a01, w0.x, hv2.x); fma2(a11, w1.x, hv2.x);
                fma2(a21, w2.x, hv2.x); fma2(a31, w3.x, hv2.x);
                fma2(a00, w0.y, hv1.y); fma2(a10, w1.y, hv1.y);
                fma2(a20, w2.y, hv1.y); fma2(a30, w3.y, hv1.y);
                fma2(a01, w0.y, hv2.y); fma2(a11, w1.y, hv2.y);
                fma2(a21, w2.y, hv2.y); fma2(a31, w3.y, hv2.y);
            }
        }

        // LSTM cell update (b1)
        {
            float gi = hsum2(a00) + inp1 * wih0 + bv0;
            float gf = hsum2(a10) + inp1 * wih1 + bv1;
            float gg = hsum2(a20) + inp1 * wih2 + bv2;
            float go = hsum2(a30) + inp1 * wih3 + bv3;
            float iv = sigmoidf(gi), fv = sigmoidf(gf), gv = tanhf(gg), ov = sigmoidf(go);
            c1 = fv * c1 + iv * gv;
            float hn = ov * tanhf(c1);
            hout[b1 * HID + u] = hn;
            if (!enc) ypart[ul][b1] = hn * fcw;
        }
        // LSTM cell update (b2)
        {
            float gi = hsum2(a01) + inp2 * wih0 + bv0;
            float gf = hsum2(a11) + inp2 * wih1 + bv1;
            float gg = hsum2(a21) + inp2 * wih2 + bv2;
            float go = hsum2(a31) + inp2 * wih3 + bv3;
            float iv = sigmoidf(gi), fv = sigmoidf(gf), gv = tanhf(gg), ov = sigmoidf(go);
            c2 = fv * c2 + iv * gv;
            float hn = ov * tanhf(c2);
            hout[b2 * HID + u] = hn;
            if (!enc) ypart[ul][b2] = hn * fcw;
        }

        if (!enc) {
            __syncthreads();
            if (tid < BSZ) {
                float s = 0.0f;
                #pragma unroll
                for (int uu = 0; uu < UPB; ++uu) s += ypart[uu][tid];
                g_yblk[blk * BSZ + tid] = s;
            }
        }

        grid_barrier(++bars);
    }

    // final output y_63
    if (blk == 0 && tid < BSZ) {
        float s = fcb0;
        #pragma unroll 8
        for (int g = 0; g < GRID; ++g) s += g_yblk[g * BSZ + tid];
        out[tid * TOUT + (TOUT - 1)] = s;
    }

    // barrier-counter cleanup for next launch (graph replay)
    __syncthreads();
    if (tid == 0) {
        unsigned o = atomicAdd(&g_fin, 1u);
        if (o == GRID - 1) {
            g_bar = 0u;
            g_fin = 0u;
            __threadfence();
        }
    }
}

extern "C" void kernel_launch(void* const* d_in, const int* in_sizes, int n_in,
                              void* d_out, int out_size) {
    const float* x    = (const float*)d_in[0];
    // d_in[1] = target (unused, teacher_forcing_ratio = 0)
    const float* eWih = (const float*)d_in[2];
    const float* eWhh = (const float*)d_in[3];
    const float* eb   = (const float*)d_in[4];
    const float* dWih = (const float*)d_in[5];
    const float* dWhh = (const float*)d_in[6];
    const float* db   = (const float*)d_in[7];
    const float* fcW  = (const float*)d_in[8];
    const float* fcb  = (const float*)d_in[9];
    float* out = (float*)d_out;

    lstm_seq2seq_kernel<<<GRID, NTHR>>>(x, eWih, eWhh, eb, dWih, dWhh, db, fcW, fcb, out);
}

// round 13
// speedup vs baseline: 1.8206x; 1.8206x over previous
#include <cuda_runtime.h>
#include <stdint.h>

// Seq2seq LSTM, persistent kernel, FMA-bound register-tile GEMM.
// 128 blocks x 256 threads. Block owns 16 units (64 gate rows) x 32 batches.
// k split across 8 warps; thread = 8 rows x 8 batches packed-k accumulators.
// Weights staged coalesced via cp.async.cg, double-buffered 128-k chunks.

#define GRID   128
#define NTHR   256
#define BSZ    32
#define HID    2048
#define TIN    128
#define TOUT   64
#define TSTEPS 192
#define UPB    16
#define KC     128
#define NCH    16

// dynamic smem float offsets
#define SM_W   0            // 2 x 8192 floats (w chunk double buffer)
#define SM_H   16384        // 2 x 4096 floats (h chunk double buffer)
#define SM_GP  24576        // 16384 floats: [8 warp][64 cell][32 lane]
#define SM_GS  40960        // 2048 floats: gate sums [64 row][32 b] xor-swizzled
#define SM_YP  43008        // 16*33
#define SM_YS  43536        // 32
#define SM_X   43600        // 4096 floats: x transposed [t][b]
#define SM_FLOATS 47700     // 190800 B

__device__ __align__(16) float g_hA[BSZ * HID];
__device__ __align__(16) float g_hB[BSZ * HID];
__device__ float    g_yblk[GRID * BSZ];
__device__ unsigned g_bar, g_fin;

__device__ __forceinline__ void fma2(unsigned long long& d,
                                     unsigned long long a,
                                     unsigned long long b) {
    asm("fma.rn.f32x2 %0, %1, %2, %0;" : "+l"(d) : "l"(a), "l"(b));
}
__device__ __forceinline__ float hsum2(unsigned long long v) {
    return __uint_as_float((unsigned)v) + __uint_as_float((unsigned)(v >> 32));
}
__device__ __forceinline__ float sigmoidf(float v) { return 1.0f / (1.0f + __expf(-v)); }

__device__ __forceinline__ uint32_t smem_u32(const void* p) {
    uint32_t a;
    asm("{ .reg .u64 t; cvta.to.shared.u64 t, %1; cvt.u32.u64 %0, t; }" : "=r"(a) : "l"(p));
    return a;
}
__device__ __forceinline__ void cp16(uint32_t dst, const void* src) {
    asm volatile("cp.async.cg.shared.global [%0], [%1], 16;" :: "r"(dst), "l"(src));
}
#define CP_COMMIT() asm volatile("cp.async.commit_group;" ::: "memory")
#define CP_WAIT(n)  asm volatile("cp.async.wait_group %0;" :: "n"(n) : "memory")

__device__ __forceinline__ void grid_barrier(int n) {
    __syncthreads();
    if (threadIdx.x == 0) {
        __threadfence();
        atomicAdd(&g_bar, 1u);
        unsigned target = (unsigned)n * GRID, v;
        do {
            asm volatile("ld.acquire.gpu.global.u32 %0, [%1];" : "=r"(v) : "l"(&g_bar) : "memory");
        } while (v < target);
    }
    __syncthreads();
}

__global__ void __launch_bounds__(NTHR, 1)
lstm_seq2seq_kernel(const float* __restrict__ x,
                    const float* __restrict__ eWih, const float* __restrict__ eWhh,
                    const float* __restrict__ eb,
                    const float* __restrict__ dWih, const float* __restrict__ dWhh,
                    const float* __restrict__ db,
                    const float* __restrict__ fcW,  const float* __restrict__ fcb,
                    float* __restrict__ out) {
    extern __shared__ __align__(16) float smem[];
    const int tid  = threadIdx.x;
    const int blk  = blockIdx.x;
    const int wid  = tid >> 5;
    const int lane = tid & 31;
    const int rg   = lane >> 2;     // row group 0..7  (rows rg*8..rg*8+7)
    const int bg   = lane & 3;      // batch group 0..3 (batches bg*8..bg*8+7)
    const int ubase = blk * UPB;

    const uint32_t sw = smem_u32(smem + SM_W);
    const uint32_t sh = smem_u32(smem + SM_H);

    // cell-update ownership: cells (ul,b) = (wid, lane) and (wid+8, lane)
    const int cb = lane;
    float cst0 = 0.0f, cst1 = 0.0f;
    g_hA[cb * HID + ubase + wid]     = 0.0f;
    g_hA[cb * HID + ubase + wid + 8] = 0.0f;

    const float fcb0 = fcb[0];
    const float fcw0 = fcW[ubase + wid];
    const float fcw1 = fcW[ubase + wid + 8];
    float wihv[2][4], biav[2][4];

    // stage x transposed: xs[t*32 + b]
    #pragma unroll
    for (int i = 0; i < 16; ++i) {
        int id = tid + i * NTHR;            // 0..4095
        int b = id >> 7, tt = id & 127;
        smem[SM_X + tt * 32 + b] = x[id];
    }

    // prefetch w chunk 0 of step 0
    #pragma unroll
    for (int i = 0; i < 8; ++i) {
        int id = tid + i * NTHR;            // 0..2047
        int row = id >> 5, k4q = id & 31;
        int g = row >> 4, ul = row & 15;
        cp16(sw + (uint32_t)(row * 512 + ((k4q ^ (row >> 3)) << 4)),
             eWhh + (size_t)(g * HID + ubase + ul) * HID + k4q * 4);
    }
    CP_COMMIT();

    int bars = 0;
    grid_barrier(++bars);   // h init + x staging visible

    for (int t = 0; t < TSTEPS; ++t) {
        const bool enc = (t < TIN);
        if (t == 0 || t == TIN) {
            const float* Wih = enc ? eWih : dWih;
            const float* bia = enc ? eb   : db;
            #pragma unroll
            for (int m = 0; m < 2; ++m)
                #pragma unroll
                for (int g = 0; g < 4; ++g) {
                    wihv[m][g] = Wih[g * HID + ubase + wid + m * 8];
                    biav[m][g] = bia[g * HID + ubase + wid + m * 8];
                }
        }
        const float* Whh  = enc ? eWhh : dWhh;
        const float* hin  = (t & 1) ? g_hB : g_hA;
        float*       hout = (t & 1) ? g_hA : g_hB;

        // decoder feedback: reduce previous step's y partials
        if (t > TIN) {
            if (tid < BSZ) {
                float s = fcb0;
                #pragma unroll 8
                for (int g = 0; g < GRID; ++g) s += g_yblk[g * BSZ + tid];
                smem[SM_YS + tid] = s;
                if (blk == 0) out[tid * TOUT + (t - 1 - TIN)] = s;
            }
            __syncthreads();
        }

        // stage h chunk 0
        #pragma unroll
        for (int i = 0; i < 4; ++i) {
            int id = tid + i * NTHR;        // 0..1023
            int b = id >> 5, k4q = id & 31;
            cp16(sh + (uint32_t)(b * 512 + ((k4q ^ (b >> 3)) << 4)),
                 hin + b * HID + k4q * 4);
        }
        CP_COMMIT();

        unsigned long long acc[8][8];
        #pragma unroll
        for (int i = 0; i < 8; ++i)
            #pragma unroll
            for (int j = 0; j < 8; ++j) acc[i][j] = 0ull;

        #pragma unroll 1
        for (int c = 0; c < NCH; ++c) {
            if (c + 1 < NCH) {
                const int cn = c + 1;
                const uint32_t wdst = sw + (uint32_t)((cn & 1) * 32768);
                const uint32_t hdst = sh + (uint32_t)((cn & 1) * 16384);
                #pragma unroll
                for (int i = 0; i < 8; ++i) {
                    int id = tid + i * NTHR;
                    int row = id >> 5, k4q = id & 31;
                    int g = row >> 4, ul = row & 15;
                    cp16(wdst + (uint32_t)(row * 512 + ((k4q ^ (row >> 3)) << 4)),
                         Whh + (size_t)(g * HID + ubase + ul) * HID + cn * KC + k4q * 4);
                }
                #pragma unroll
                for (int i = 0; i < 4; ++i) {
                    int id = tid + i * NTHR;
                    int b = id >> 5, k4q = id & 31;
                    cp16(hdst + (uint32_t)(b * 512 + ((k4q ^ (b >> 3)) << 4)),
                         hin + b * HID + cn * KC + k4q * 4);
                }
                CP_COMMIT();
                CP_WAIT(1);
            } else {
                CP_WAIT(0);
            }
            __syncthreads();

            const float* wb = smem + SM_W + (c & 1) * 8192;
            const float* hb = smem + SM_H + (c & 1) * 4096;
            #pragma unroll
            for (int q = 0; q < 4; ++q) {
                const int k4q = wid * 4 + q;
                ulonglong2 hv[8];
                #pragma unroll
                for (int j = 0; j < 8; ++j)
                    hv[j] = *reinterpret_cast<const ulonglong2*>(
                        hb + (bg * 8 + j) * 128 + ((k4q ^ bg) << 2));
                #pragma unroll
                for (int i = 0; i < 8; ++i) {
                    ulonglong2 wv = *reinterpret_cast<const ulonglong2*>(
                        wb + (rg * 8 + i) * 128 + ((k4q ^ rg) << 2));
                    #pragma unroll
                    for (int j = 0; j < 8; ++j) {
                        fma2(acc[i][j], wv.x, hv[j].x);
                        fma2(acc[i][j], wv.y, hv[j].y);
                    }
                }
            }
            __syncthreads();
        }

        // ---- epilogue ----
        // 1. per-warp partials -> smem
        {
            float* gp = smem + SM_GP + wid * 2048;
            #pragma unroll
            for (int i = 0; i < 8; ++i)
                #pragma unroll
                for (int j = 0; j < 8; ++j)
                    gp[(i * 8 + j) * 32 + lane] = hsum2(acc[i][j]);
        }
        __syncthreads();
        // 2. cross-warp k reduction -> gsum[row*32 + (b ^ (row>>3))]
        #pragma unroll
        for (int m = 0; m < 8; ++m) {
            int cp = tid + m * NTHR;
            float s = 0.0f;
            #pragma unroll
            for (int w = 0; w < 8; ++w) s += smem[SM_GP + w * 2048 + cp];
            int i = (cp >> 8) & 7, j = (cp >> 5) & 7, ln = cp & 31;
            int row = (ln >> 2) * 8 + i;
            int b   = (ln & 3) * 8 + j;
            smem[SM_GS + row * 32 + (b ^ (row >> 3))] = s;
        }
        __syncthreads();
        // 3. cell updates (2 per thread), c in registers
        {
            float inp;
            if (enc)            inp = smem[SM_X + t * 32 + cb];
            else if (t == TIN)  inp = smem[SM_X + (TIN - 1) * 32 + cb];
            else                inp = smem[SM_YS + cb];
            #pragma unroll
            for (int m = 0; m < 2; ++m) {
                const int ul = wid + m * 8;
                const int u  = ubase + ul;
                float gate[4];
                #pragma unroll
                for (int g = 0; g < 4; ++g) {
                    int row = g * 16 + ul;
                    gate[g] = smem[SM_GS + row * 32 + (cb ^ (row >> 3))]
                            + inp * wihv[m][g] + biav[m][g];
                }
                float iv = sigmoidf(gate[0]), fv = sigmoidf(gate[1]);
                float gv = tanhf(gate[2]),   ov = sigmoidf(gate[3]);
                float cold = m ? cst1 : cst0;
                float cn = fv * cold + iv * gv;
                if (m) cst1 = cn; else cst0 = cn;
                float hn = ov * tanhf(cn);
                hout[cb * HID + u] = hn;
                if (!enc) smem[SM_YP + ul * 33 + cb] = hn * (m ? fcw1 : fcw0);
            }
        }
        if (!enc) {
            __syncthreads();
            if (tid < BSZ) {
                float s = 0.0f;
                #pragma unroll
                for (int ul = 0; ul < UPB; ++ul) s += smem[SM_YP + ul * 33 + tid];
                g_yblk[blk * BSZ + tid] = s;
            }
        }

        // prefetch w chunk 0 of next step (buffer 0 is free: last used at c=14)
        if (t + 1 < TSTEPS) {
            const float* Wn = (t + 1 < TIN) ? eWhh : dWhh;
            #pragma unroll
            for (int i = 0; i < 8; ++i) {
                int id = tid + i * NTHR;
                int row = id >> 5, k4q = id & 31;
                int g = row >> 4, ul = row & 15;
                cp16(sw + (uint32_t)(row * 512 + ((k4q ^ (row >> 3)) << 4)),
                     Wn + (size_t)(g * HID + ubase + ul) * HID + k4q * 4);
            }
            CP_COMMIT();
        }
        grid_barrier(++bars);
    }

    // final output y_63
    if (blk == 0 && tid < BSZ) {
        float s = fcb0;
        #pragma unroll 8
        for (int g = 0; g < GRID; ++g) s += g_yblk[g * BSZ + tid];
        out[tid * TOUT + (TOUT - 1)] = s;
    }

    // barrier cleanup for graph replay
    __syncthreads();
    if (tid == 0) {
        unsigned o = atomicAdd(&g_fin, 1u);
        if (o == GRID - 1) { g_bar = 0u; g_fin = 0u; __threadfence(); }
    }
}

extern "C" void kernel_launch(void* const* d_in, const int* in_sizes, int n_in,
                              void* d_out, int out_size) {
    const float* x    = (const float*)d_in[0];
    const float* eWih = (const float*)d_in[2];
    const float* eWhh = (const float*)d_in[3];
    const float* eb   = (const float*)d_in[4];
    const float* dWih = (const float*)d_in[5];
    const float* dWhh = (const float*)d_in[6];
    const float* db   = (const float*)d_in[7];
    const float* fcW  = (const float*)d_in[8];
    const float* fcb  = (const float*)d_in[9];
    float* out = (float*)d_out;

    cudaFuncSetAttribute(lstm_seq2seq_kernel,
                         cudaFuncAttributeMaxDynamicSharedMemorySize,
                         SM_FLOATS * 4);
    lstm_seq2seq_kernel<<<GRID, NTHR, SM_FLOATS * 4>>>(
        x, eWih, eWhh, eb, dWih, dWhh, db, fcW, fcb, out);
}